// round 1
// baseline (speedup 1.0000x reference)
#include <cuda_runtime.h>
#include <cstdint>

#define FULLMASK 0xffffffffu
#define SENT 0xFFFFFFFFu

// ---------------- global scratch (no allocs allowed) ----------------
__device__ double g_reg, g_cls, g_obj;
__device__ unsigned long long g_pc, g_objt;
#define MASK_WORDS 10752   // 8192 (L0) + 2048 (L1) + 512 (L2)
__device__ unsigned int g_mask[MASK_WORDS];

// stable softplus, matches jax.nn.softplus
__device__ __forceinline__ float sp(float x){
    return fmaxf(x, 0.0f) + log1pf(expf(-fabsf(x)));
}

__device__ __forceinline__ float segd(float px,float py,float x1,float y1,float x2,float y2){
    float vx=x2-x1, vy=y2-y1;
    float wx=px-x1, wy=py-y1;
    float t = (wx*vx+wy*vy)/(vx*vx+vy*vy+1e-9f);
    t = fminf(fmaxf(t,0.0f),1.0f);
    float dx = px - (x1 + t*vx);
    float dy = py - (y1 + t*vy);
    return sqrtf(dx*dx+dy*dy+1e-12f);
}

// One block per (b,g). HW == BLOCK*CPT exactly.
template<int BLOCK,int CPT,int H,int W>
__global__ __launch_bounds__(BLOCK) void level_kernel(
    const float* __restrict__ preg,
    const float* __restrict__ pcls,
    const float* __restrict__ gt,
    float stride, int mask_off)
{
    constexpr int HW = H*W;
    const int b   = blockIdx.x >> 5;   // Ng = 32
    const int tid = threadIdx.x;
    const int lane = tid & 31;

    const float* t = gt + (size_t)blockIdx.x * 6;
    float Ax=t[0],Ay=t[1],Bx=t[2],By=t[3],Cx=t[4],Cy=t[5];

    // bbox expanded by ETA(=3) -> cell window (conservative +/-1 cell)
    float xmn = fminf(Ax,fminf(Bx,Cx)) - 3.0f;
    float xmx = fmaxf(Ax,fmaxf(Bx,Cx)) + 3.0f;
    float ymn = fminf(Ay,fminf(By,Cy)) - 3.0f;
    float ymx = fmaxf(Ay,fmaxf(By,Cy)) + 3.0f;
    float inv = 1.0f/stride;
    int w0 = max(0,   (int)floorf(xmn*inv - 0.5f) - 1);
    int w1 = min(W-1, (int)ceilf (xmx*inv - 0.5f) + 1);
    int h0 = max(0,   (int)floorf(ymn*inv - 0.5f) - 1);
    int h1 = min(H-1, (int)ceilf (ymx*inv - 0.5f) + 1);

    unsigned int keys[CPT];
    int poscnt = 0;
    #pragma unroll
    for (int i=0;i<CPT;i++){
        int idx = tid + i*BLOCK;
        int hh = idx / W;
        int ww = idx - hh*W;
        unsigned int key = SENT;
        if (ww>=w0 && ww<=w1 && hh>=h0 && hh<=h1){
            float px = (ww+0.5f)*stride;
            float py = (hh+0.5f)*stride;
            float d1 = (px-Bx)*(Ay-By) - (Ax-Bx)*(py-By);
            float d2 = (px-Cx)*(By-Cy) - (Bx-Cx)*(py-Cy);
            float d3 = (px-Ax)*(Cy-Ay) - (Cx-Ax)*(py-Ay);
            bool hneg = (d1<0.f)||(d2<0.f)||(d3<0.f);
            bool hpos = (d1>0.f)||(d2>0.f)||(d3>0.f);
            bool inside = !(hneg&&hpos);
            float dist = fminf(segd(px,py,Ax,Ay,Bx,By),
                         fminf(segd(px,py,Bx,By,Cx,Cy),
                               segd(px,py,Cx,Cy,Ax,Ay)));
            if (inside || dist<=3.0f){ key = __float_as_uint(dist); poscnt++; }
        }
        keys[i]=key;
    }

    __shared__ unsigned int sh_hist[256];
    __shared__ unsigned int sh_total;
    __shared__ unsigned int sh_sel, sh_newk, sh_selcnt;
    __shared__ unsigned long long sh_kth;

    if (tid==0) sh_total = 0;
    __syncthreads();
    // warp-reduce pos count, one shared atomic per warp
    {
        int pc = poscnt;
        for (int off=16;off;off>>=1) pc += __shfl_xor_sync(FULLMASK,pc,off);
        if (lane==0 && pc) atomicAdd(&sh_total,(unsigned)pc);
    }
    __syncthreads();
    const bool accept_all = (sh_total <= 96u);

    unsigned long long kth = ~0ull;
    if (!accept_all){
        // radix select on 48-bit key = (dist_bits << 14) | idx  (exact jax tie-break)
        unsigned long long pref = 0;
        int k = 96;
        bool done = false;
        for (int shift=40; shift>=0 && !done; shift-=8){
            for (int j=tid;j<256;j+=BLOCK) sh_hist[j]=0;
            __syncthreads();
            #pragma unroll
            for (int i=0;i<CPT;i++){
                unsigned int kk = keys[i];
                int idx = tid + i*BLOCK;
                unsigned long long k64 = ((unsigned long long)kk<<14) | (unsigned)idx;
                bool part = (kk!=SENT) && ((k64>>(shift+8))==pref);
                unsigned int bin = part ? (unsigned)((k64>>shift)&0xFF) : 0xFFFFFFFFu;
                unsigned int mm = __match_any_sync(FULLMASK, bin);
                if (part && lane == (__ffs(mm)-1))
                    atomicAdd(&sh_hist[bin], (unsigned)__popc(mm));
            }
            __syncthreads();
            // warp-0 scan of 256 bins (8 bins per lane + shfl scan)
            if (tid < 32){
                unsigned v[8]; unsigned run=0;
                #pragma unroll
                for (int u=0;u<8;u++){ run += sh_hist[lane*8+u]; v[u]=run; }
                unsigned p = run;
                #pragma unroll
                for (int off=1;off<32;off<<=1){
                    unsigned n = __shfl_up_sync(FULLMASK,p,off);
                    if (lane>=off) p += n;
                }
                unsigned excl = p - run;
                #pragma unroll
                for (int u=0;u<8;u++){
                    unsigned cum  = excl + v[u];
                    unsigned prev = excl + (u? v[u-1] : 0u);
                    if (cum >= (unsigned)k && prev < (unsigned)k){
                        sh_sel = lane*8+u; sh_newk = k - prev; sh_selcnt = cum - prev;
                    }
                }
            }
            __syncthreads();
            unsigned sel = sh_sel; k = (int)sh_newk; unsigned cnt = sh_selcnt;
            pref = (pref<<8) | sel;
            if (cnt == 1u){
                // unique key owns this prefix -> it IS the k-th; find it
                #pragma unroll
                for (int i=0;i<CPT;i++){
                    unsigned int kk = keys[i];
                    if (kk!=SENT){
                        int idx = tid + i*BLOCK;
                        unsigned long long k64 = ((unsigned long long)kk<<14)|(unsigned)idx;
                        if ((k64>>shift)==pref) sh_kth = k64;
                    }
                }
                done = true;
            } else if (shift==0){
                if (tid==0) sh_kth = pref;
            }
            __syncthreads();
        }
        kth = sh_kth;
    }

    // accumulation pass over accepted cells
    float regsum=0.f, clssum=0.f; int cnt=0;
    const float* rbase = preg + (size_t)b*6*HW;
    const float* cbase = pcls + (size_t)b*HW;
    unsigned int* mbase = g_mask + mask_off + b*(HW>>5);
    #pragma unroll
    for (int i=0;i<CPT;i++){
        unsigned int kk = keys[i];
        if (kk==SENT) continue;
        int idx = tid + i*BLOCK;
        unsigned long long k64 = ((unsigned long long)kk<<14)|(unsigned)idx;
        if (!accept_all && k64 > kth) continue;
        int hh = idx / W, ww = idx - hh*W;
        float px=(ww+0.5f)*stride, py=(hh+0.5f)*stride;
        float g0x=(Ax-px)*inv, g0y=(Ay-py)*inv;
        float g1x=(Bx-px)*inv, g1y=(By-py)*inv;
        float g2x=(Cx-px)*inv, g2y=(Cy-py)*inv;
        float p0x = rbase[idx],        p0y = rbase[HW+idx];
        float p1x = rbase[2*HW+idx],   p1y = rbase[3*HW+idx];
        float p2x = rbase[4*HW+idx],   p2y = rbase[5*HW+idx];
        float p0 = (p0x-g0x)*(p0x-g0x) + (p0y-g0y)*(p0y-g0y);
        float d00 = sqrtf((p1x-g1x)*(p1x-g1x)+(p1y-g1y)*(p1y-g1y));
        float d01 = sqrtf((p1x-g2x)*(p1x-g2x)+(p1y-g2y)*(p1y-g2y));
        float d10 = sqrtf((p2x-g1x)*(p2x-g1x)+(p2y-g1y)*(p2y-g1y));
        float d11 = sqrtf((p2x-g2x)*(p2x-g2x)+(p2y-g2y)*(p2y-g2y));
        float cd = fminf(d00,d01)+fminf(d10,d11)+fminf(d00,d10)+fminf(d01,d11);
        regsum += p0 + cd;            // LAMBDA_P0 = LAMBDA_CD = 1
        clssum += sp(-cbase[idx]);
        cnt++;
        atomicOr(&mbase[idx>>5], 1u<<(idx&31));
    }
    for (int off=16;off;off>>=1){
        regsum += __shfl_xor_sync(FULLMASK,regsum,off);
        clssum += __shfl_xor_sync(FULLMASK,clssum,off);
        cnt    += __shfl_xor_sync(FULLMASK,cnt,off);
    }
    __shared__ float s_reg, s_cls; __shared__ int s_cnt;
    if (tid==0){ s_reg=0.f; s_cls=0.f; s_cnt=0; }
    __syncthreads();
    if (lane==0 && cnt){
        atomicAdd(&s_reg,regsum); atomicAdd(&s_cls,clssum); atomicAdd(&s_cnt,cnt);
    }
    __syncthreads();
    if (tid==0 && s_cnt){
        atomicAdd(&g_reg,(double)s_reg);
        atomicAdd(&g_cls,(double)s_cls);
        atomicAdd(&g_pc,(unsigned long long)s_cnt);
    }
}

template<int HW>
__global__ __launch_bounds__(256) void obj_kernel(const float* __restrict__ pobj, int mask_off)
{
    const int tid = threadIdx.x;
    const int lane = tid & 31;
    float sum = 0.f; int ot = 0;
    const int total = 16*HW;
    for (int i = blockIdx.x*256 + tid; i < total; i += gridDim.x*256){
        int b = i / HW; int hw = i - b*HW;
        unsigned wrd = g_mask[mask_off + b*(HW>>5) + (hw>>5)];
        unsigned bit = (wrd >> (hw&31)) & 1u;
        float x = pobj[i];
        sum += bit ? 1.2f*sp(-x) : sp(x);
        ot  += (int)bit;
    }
    for (int off=16;off;off>>=1){
        sum += __shfl_xor_sync(FULLMASK,sum,off);
        ot  += __shfl_xor_sync(FULLMASK,ot,off);
    }
    __shared__ float s_sum; __shared__ int s_ot;
    if (tid==0){ s_sum=0.f; s_ot=0; }
    __syncthreads();
    if (lane==0){ atomicAdd(&s_sum,sum); atomicAdd(&s_ot,ot); }
    __syncthreads();
    if (tid==0){
        atomicAdd(&g_obj,(double)s_sum);
        atomicAdd(&g_objt,(unsigned long long)s_ot);
    }
}

__global__ void zero_kernel(){
    int i = blockIdx.x*blockDim.x+threadIdx.x;
    if (i==0){ g_reg=0.0; g_cls=0.0; g_obj=0.0; g_pc=0ull; g_objt=0ull; }
    for (int j=i; j<MASK_WORDS; j+=blockDim.x*gridDim.x) g_mask[j]=0u;
}

__global__ void finalize_kernel(float* out){
    double pc = (double)g_pc; if (pc < 1.0) pc = 1.0;
    double nc = 344064.0 - (double)g_objt; if (nc < 1.0) nc = 1.0;
    out[0] = (float)(g_reg/pc + g_obj/(pc+nc) + g_cls/pc);
}

extern "C" void kernel_launch(void* const* d_in, const int* in_sizes, int n_in,
                              void* d_out, int out_size)
{
    const float* reg0 = (const float*)d_in[0];
    const float* obj0 = (const float*)d_in[1];
    const float* cls0 = (const float*)d_in[2];
    const float* reg1 = (const float*)d_in[3];
    const float* obj1 = (const float*)d_in[4];
    const float* cls1 = (const float*)d_in[5];
    const float* reg2 = (const float*)d_in[6];
    const float* obj2 = (const float*)d_in[7];
    const float* cls2 = (const float*)d_in[8];
    const float* gt   = (const float*)d_in[9];
    float* out = (float*)d_out;

    zero_kernel<<<42,256>>>();
    level_kernel<1024,16,128,128><<<512,1024>>>(reg0, cls0, gt,  8.0f, 0);
    level_kernel< 256,16, 64, 64><<<512, 256>>>(reg1, cls1, gt, 16.0f, 8192);
    level_kernel< 256, 4, 32, 32><<<512, 256>>>(reg2, cls2, gt, 32.0f, 10240);
    obj_kernel<16384><<<256,256>>>(obj0, 0);
    obj_kernel< 4096><<< 64,256>>>(obj1, 8192);
    obj_kernel< 1024><<< 16,256>>>(obj2, 10240);
    finalize_kernel<<<1,1>>>(out);
}

// round 2
// speedup vs baseline: 2.6972x; 2.6972x over previous
#include <cuda_runtime.h>
#include <cstdint>

#define FULLMASK 0xffffffffu
#define CAP 9216          // hard upper bound on candidates per (b,g) at L0

// ---------------- global scratch (no allocs allowed) ----------------
__device__ double g_reg, g_cls, g_obj;
__device__ unsigned long long g_pc, g_objt;
#define MASK_WORDS 10752   // 8192 (L0) + 2048 (L1) + 512 (L2)
__device__ unsigned int g_mask[MASK_WORDS];

// stable softplus, matches jax.nn.softplus
__device__ __forceinline__ float sp(float x){
    return fmaxf(x, 0.0f) + log1pf(expf(-fabsf(x)));
}

__device__ __forceinline__ float segd(float px,float py,float x1,float y1,float x2,float y2){
    float vx=x2-x1, vy=y2-y1;
    float wx=px-x1, wy=py-y1;
    float t = (wx*vx+wy*vy)/(vx*vx+vy*vy+1e-9f);
    t = fminf(fmaxf(t,0.0f),1.0f);
    float dx = px - (x1 + t*vx);
    float dy = py - (y1 + t*vy);
    return sqrtf(dx*dx+dy*dy+1e-12f);
}

// One block per (level, b, g). 1536 blocks total; L0 first (largest work).
__global__ __launch_bounds__(256) void level_all(
    const float* __restrict__ reg0, const float* __restrict__ cls0,
    const float* __restrict__ reg1, const float* __restrict__ cls1,
    const float* __restrict__ reg2, const float* __restrict__ cls2,
    const float* __restrict__ gt)
{
    extern __shared__ unsigned long long buf[];              // CAP entries
    unsigned int* sh_hist = (unsigned int*)(buf + CAP);      // 256 bins
    __shared__ unsigned int sh_n, sh_sel, sh_newk, sh_selcnt;
    __shared__ unsigned long long sh_kth;
    __shared__ float s_reg, s_cls; __shared__ int s_cnt;

    const int lv   = blockIdx.x >> 9;
    const int pair = blockIdx.x & 511;
    const int b    = pair >> 5;            // Ng = 32
    const int tid  = threadIdx.x;
    const int lane = tid & 31;

    int W, logW, moff; float stride;
    const float *preg, *pcls;
    if (lv==0){ W=128; logW=7; moff=0;     stride= 8.f; preg=reg0; pcls=cls0; }
    else if (lv==1){ W=64; logW=6; moff=8192;  stride=16.f; preg=reg1; pcls=cls1; }
    else       { W=32; logW=5; moff=10240; stride=32.f; preg=reg2; pcls=cls2; }
    const int H  = W;
    const int HW = 1 << (2*logW);

    if (tid==0){ sh_n=0; s_reg=0.f; s_cls=0.f; s_cnt=0; }
    __syncthreads();

    const float* t = gt + (size_t)pair * 6;
    float Ax=t[0],Ay=t[1],Bx=t[2],By=t[3],Cx=t[4],Cy=t[5];

    // bbox expanded by ETA(=3) -> cell window (conservative +/-1 cell)
    float xmn = fminf(Ax,fminf(Bx,Cx)) - 3.0f;
    float xmx = fmaxf(Ax,fmaxf(Bx,Cx)) + 3.0f;
    float ymn = fminf(Ay,fminf(By,Cy)) - 3.0f;
    float ymx = fmaxf(Ay,fmaxf(By,Cy)) + 3.0f;
    float inv = 1.0f/stride;
    int w0 = max(0,   (int)floorf(xmn*inv - 0.5f) - 1);
    int w1 = min(W-1, (int)ceilf (xmx*inv - 0.5f) + 1);
    int h0 = max(0,   (int)floorf(ymn*inv - 0.5f) - 1);
    int h1 = min(H-1, (int)ceilf (ymx*inv - 0.5f) + 1);
    int winW = w1 - w0 + 1;
    int winH = h1 - h0 + 1;
    int winN = (winW > 0 && winH > 0) ? winW * winH : 0;

    // ---- phase 1: geometry over window, compact candidates to shared ----
    for (int j0 = 0; j0 < winN; j0 += 256){
        int j = j0 + tid;
        unsigned long long key = 0; bool cand = false;
        if (j < winN){
            int r = j / winW;
            int c = j - r*winW;
            int hh = h0 + r, ww = w0 + c;
            float px = (ww+0.5f)*stride;
            float py = (hh+0.5f)*stride;
            float d1 = (px-Bx)*(Ay-By) - (Ax-Bx)*(py-By);
            float d2 = (px-Cx)*(By-Cy) - (Bx-Cx)*(py-Cy);
            float d3 = (px-Ax)*(Cy-Ay) - (Cx-Ax)*(py-Ay);
            bool hneg = (d1<0.f)||(d2<0.f)||(d3<0.f);
            bool hpos = (d1>0.f)||(d2>0.f)||(d3>0.f);
            bool inside = !(hneg&&hpos);
            float dist = fminf(segd(px,py,Ax,Ay,Bx,By),
                         fminf(segd(px,py,Bx,By,Cx,Cy),
                               segd(px,py,Cx,Cy,Ax,Ay)));
            if (inside || dist<=3.0f){
                cand = true;
                key = ((unsigned long long)__float_as_uint(dist)<<14)
                      | (unsigned)((hh<<logW)|ww);
            }
        }
        unsigned bal = __ballot_sync(FULLMASK, cand);
        int wc = __popc(bal);
        if (wc){
            unsigned base = 0;
            if (lane==0) base = atomicAdd(&sh_n,(unsigned)wc);
            base = __shfl_sync(FULLMASK, base, 0);
            if (cand){
                unsigned pos = base + __popc(bal & ((1u<<lane)-1));
                if (pos < CAP) buf[pos] = key;
            }
        }
    }
    __syncthreads();
    const int n = (int)sh_n;
    const bool accept_all = (n <= 96);

    // ---- phase 2: radix select of 96th smallest packed key ----
    unsigned long long kth = ~0ull;
    if (!accept_all){
        unsigned long long pref = 0;
        int k = 96;
        bool done = false;
        for (int shift=40; shift>=0 && !done; shift-=8){
            sh_hist[tid] = 0;                       // 256 threads, 256 bins
            __syncthreads();
            for (int j0=0; j0<n; j0+=256){
                int j = j0 + tid;
                unsigned bin = 0xFFFFFFFFu;
                if (j < n){
                    unsigned long long key = buf[j];
                    if ((key>>(shift+8)) == pref)
                        bin = (unsigned)((key>>shift)&0xFF);
                }
                unsigned mm = __match_any_sync(FULLMASK, bin);
                if (bin != 0xFFFFFFFFu && lane == (__ffs(mm)-1))
                    atomicAdd(&sh_hist[bin], (unsigned)__popc(mm));
            }
            __syncthreads();
            if (tid < 32){
                unsigned v[8]; unsigned run=0;
                #pragma unroll
                for (int u=0;u<8;u++){ run += sh_hist[lane*8+u]; v[u]=run; }
                unsigned p = run;
                #pragma unroll
                for (int off=1;off<32;off<<=1){
                    unsigned nn = __shfl_up_sync(FULLMASK,p,off);
                    if (lane>=off) p += nn;
                }
                unsigned excl = p - run;
                #pragma unroll
                for (int u=0;u<8;u++){
                    unsigned cum  = excl + v[u];
                    unsigned prev = excl + (u? v[u-1] : 0u);
                    if (cum >= (unsigned)k && prev < (unsigned)k){
                        sh_sel = lane*8+u; sh_newk = k - prev; sh_selcnt = cum - prev;
                    }
                }
            }
            __syncthreads();
            unsigned sel = sh_sel; k = (int)sh_newk; unsigned cnt = sh_selcnt;
            pref = (pref<<8) | sel;
            if (cnt == 1u){
                for (int j=tid; j<n; j+=256){
                    unsigned long long key = buf[j];
                    if ((key>>shift) == pref) sh_kth = key;
                }
                done = true;
            } else if (shift==0){
                if (tid==0) sh_kth = pref;
            }
            __syncthreads();
        }
        kth = sh_kth;
    }

    // ---- phase 3: accumulate over accepted candidates ----
    float regsum=0.f, clssum=0.f; int cnt=0;
    const float* rbase = preg + (size_t)b*6*HW;
    const float* cbase = pcls + (size_t)b*HW;
    unsigned int* mbase = g_mask + moff + b*(HW>>5);
    for (int j=tid; j<n; j+=256){
        unsigned long long key = buf[j];
        if (!accept_all && key > kth) continue;
        int idx = (int)(key & 0x3FFFull);
        int hh = idx >> logW, ww = idx & (W-1);
        float px=(ww+0.5f)*stride, py=(hh+0.5f)*stride;
        float g0x=(Ax-px)*inv, g0y=(Ay-py)*inv;
        float g1x=(Bx-px)*inv, g1y=(By-py)*inv;
        float g2x=(Cx-px)*inv, g2y=(Cy-py)*inv;
        float p0x = rbase[idx],        p0y = rbase[HW+idx];
        float p1x = rbase[2*HW+idx],   p1y = rbase[3*HW+idx];
        float p2x = rbase[4*HW+idx],   p2y = rbase[5*HW+idx];
        float p0 = (p0x-g0x)*(p0x-g0x) + (p0y-g0y)*(p0y-g0y);
        float d00 = sqrtf((p1x-g1x)*(p1x-g1x)+(p1y-g1y)*(p1y-g1y));
        float d01 = sqrtf((p1x-g2x)*(p1x-g2x)+(p1y-g2y)*(p1y-g2y));
        float d10 = sqrtf((p2x-g1x)*(p2x-g1x)+(p2y-g1y)*(p2y-g1y));
        float d11 = sqrtf((p2x-g2x)*(p2x-g2x)+(p2y-g2y)*(p2y-g2y));
        float cd = fminf(d00,d01)+fminf(d10,d11)+fminf(d00,d10)+fminf(d01,d11);
        regsum += p0 + cd;            // LAMBDA_P0 = LAMBDA_CD = 1
        clssum += sp(-cbase[idx]);
        cnt++;
        atomicOr(&mbase[idx>>5], 1u<<(idx&31));
    }
    for (int off=16;off;off>>=1){
        regsum += __shfl_xor_sync(FULLMASK,regsum,off);
        clssum += __shfl_xor_sync(FULLMASK,clssum,off);
        cnt    += __shfl_xor_sync(FULLMASK,cnt,off);
    }
    if (lane==0 && cnt){
        atomicAdd(&s_reg,regsum); atomicAdd(&s_cls,clssum); atomicAdd(&s_cnt,cnt);
    }
    __syncthreads();
    if (tid==0 && s_cnt){
        atomicAdd(&g_reg,(double)s_reg);
        atomicAdd(&g_cls,(double)s_cls);
        atomicAdd(&g_pc,(unsigned long long)s_cnt);
    }
}

// single fused obj pass over all three levels (344064 cells total)
__global__ __launch_bounds__(256) void obj_all(
    const float* __restrict__ o0,
    const float* __restrict__ o1,
    const float* __restrict__ o2)
{
    const int tid = threadIdx.x;
    const int lane = tid & 31;
    float sum = 0.f; int ot = 0;
    for (int i = blockIdx.x*256 + tid; i < 344064; i += gridDim.x*256){
        const float* p; int local, logHW, moff;
        if (i < 262144){ p=o0; local=i;        logHW=14; moff=0;     }
        else if (i < 327680){ p=o1; local=i-262144; logHW=12; moff=8192; }
        else { p=o2; local=i-327680; logHW=10; moff=10240; }
        int b  = local >> logHW;
        int hw = local & ((1<<logHW)-1);
        unsigned wrd = g_mask[moff + b*(1<<(logHW-5)) + (hw>>5)];
        unsigned bit = (wrd >> (hw&31)) & 1u;
        float x = p[local];
        sum += bit ? 1.2f*sp(-x) : sp(x);
        ot  += (int)bit;
    }
    for (int off=16;off;off>>=1){
        sum += __shfl_xor_sync(FULLMASK,sum,off);
        ot  += __shfl_xor_sync(FULLMASK,ot,off);
    }
    __shared__ float s_sum; __shared__ int s_ot;
    if (tid==0){ s_sum=0.f; s_ot=0; }
    __syncthreads();
    if (lane==0){ atomicAdd(&s_sum,sum); atomicAdd(&s_ot,ot); }
    __syncthreads();
    if (tid==0){
        atomicAdd(&g_obj,(double)s_sum);
        atomicAdd(&g_objt,(unsigned long long)s_ot);
    }
}

__global__ void zero_kernel(){
    int i = blockIdx.x*blockDim.x+threadIdx.x;
    if (i==0){ g_reg=0.0; g_cls=0.0; g_obj=0.0; g_pc=0ull; g_objt=0ull; }
    for (int j=i; j<MASK_WORDS; j+=blockDim.x*gridDim.x) g_mask[j]=0u;
}

__global__ void finalize_kernel(float* out){
    double pc = (double)g_pc; if (pc < 1.0) pc = 1.0;
    double nc = 344064.0 - (double)g_objt; if (nc < 1.0) nc = 1.0;
    out[0] = (float)(g_reg/pc + g_obj/(pc+nc) + g_cls/pc);
}

extern "C" void kernel_launch(void* const* d_in, const int* in_sizes, int n_in,
                              void* d_out, int out_size)
{
    const float* reg0 = (const float*)d_in[0];
    const float* obj0 = (const float*)d_in[1];
    const float* cls0 = (const float*)d_in[2];
    const float* reg1 = (const float*)d_in[3];
    const float* obj1 = (const float*)d_in[4];
    const float* cls1 = (const float*)d_in[5];
    const float* reg2 = (const float*)d_in[6];
    const float* obj2 = (const float*)d_in[7];
    const float* cls2 = (const float*)d_in[8];
    const float* gt   = (const float*)d_in[9];
    float* out = (float*)d_out;

    const int smem = CAP*8 + 256*4;   // 74752 bytes
    static int attr_set = 0;
    if (!attr_set){
        cudaFuncSetAttribute(level_all,
            cudaFuncAttributeMaxDynamicSharedMemorySize, smem);
        attr_set = 1;
    }

    zero_kernel<<<42,256>>>();
    level_all<<<1536,256,smem>>>(reg0, cls0, reg1, cls1, reg2, cls2, gt);
    obj_all<<<336,256>>>(obj0, obj1, obj2);
    finalize_kernel<<<1,1>>>(out);
}

// round 3
// speedup vs baseline: 3.0900x; 1.1456x over previous
#include <cuda_runtime.h>
#include <cstdint>

#define FULLMASK 0xffffffffu
#define CAP 9216          // hard upper bound on candidates per (b,g) at L0
#define LBLOCK 512
#define OBJ_BLOCKS 336

// ---------------- global scratch (no allocs allowed) ----------------
__device__ double g_reg, g_cls, g_obj;
__device__ unsigned long long g_pc, g_objt;
__device__ unsigned int g_done;
#define MASK_WORDS 10752   // 8192 (L0) + 2048 (L1) + 512 (L2)
__device__ unsigned int g_mask[MASK_WORDS];

// stable softplus, matches jax.nn.softplus
__device__ __forceinline__ float sp(float x){
    return fmaxf(x, 0.0f) + log1pf(expf(-fabsf(x)));
}

__device__ __forceinline__ float segd(float px,float py,float x1,float y1,float x2,float y2){
    float vx=x2-x1, vy=y2-y1;
    float wx=px-x1, wy=py-y1;
    float t = (wx*vx+wy*vy)/(vx*vx+vy*vy+1e-9f);
    t = fminf(fmaxf(t,0.0f),1.0f);
    float dx = px - (x1 + t*vx);
    float dy = py - (y1 + t*vy);
    return sqrtf(dx*dx+dy*dy+1e-12f);
}

// One block per (level, b, g). 1536 blocks; L0 first (largest work).
__global__ __launch_bounds__(LBLOCK) void level_all(
    const float* __restrict__ reg0, const float* __restrict__ cls0,
    const float* __restrict__ reg1, const float* __restrict__ cls1,
    const float* __restrict__ reg2, const float* __restrict__ cls2,
    const float* __restrict__ gt)
{
    extern __shared__ unsigned int smem_raw[];
    unsigned int*      sdist  = smem_raw;                    // CAP u32
    unsigned int*      sh_hist= smem_raw + CAP;              // 256 u32
    unsigned short*    sidx   = (unsigned short*)(smem_raw + CAP + 256); // CAP u16
    __shared__ unsigned int sh_n, sh_sel, sh_newk, sh_selcnt, sh_kd;
    __shared__ float s_reg, s_cls; __shared__ int s_cnt;

    const int lv   = blockIdx.x >> 9;
    const int pair = blockIdx.x & 511;
    const int b    = pair >> 5;            // Ng = 32
    const int tid  = threadIdx.x;
    const int lane = tid & 31;

    int W, logW, moff; float stride;
    const float *preg, *pcls;
    if (lv==0){ W=128; logW=7; moff=0;     stride= 8.f; preg=reg0; pcls=cls0; }
    else if (lv==1){ W=64; logW=6; moff=8192;  stride=16.f; preg=reg1; pcls=cls1; }
    else       { W=32; logW=5; moff=10240; stride=32.f; preg=reg2; pcls=cls2; }
    const int H  = W;
    const int HW = 1 << (2*logW);

    if (tid==0){ sh_n=0; s_reg=0.f; s_cls=0.f; s_cnt=0; }
    __syncthreads();

    const float* t = gt + (size_t)pair * 6;
    float Ax=t[0],Ay=t[1],Bx=t[2],By=t[3],Cx=t[4],Cy=t[5];

    // bbox expanded by ETA(=3) -> cell window (conservative +/-1 cell)
    float xmn = fminf(Ax,fminf(Bx,Cx)) - 3.0f;
    float xmx = fmaxf(Ax,fmaxf(Bx,Cx)) + 3.0f;
    float ymn = fminf(Ay,fminf(By,Cy)) - 3.0f;
    float ymx = fmaxf(Ay,fmaxf(By,Cy)) + 3.0f;
    float inv = 1.0f/stride;
    int w0 = max(0,   (int)floorf(xmn*inv - 0.5f) - 1);
    int w1 = min(W-1, (int)ceilf (xmx*inv - 0.5f) + 1);
    int h0 = max(0,   (int)floorf(ymn*inv - 0.5f) - 1);
    int h1 = min(H-1, (int)ceilf (ymx*inv - 0.5f) + 1);
    int winW = w1 - w0 + 1;
    int winH = h1 - h0 + 1;
    int winN = (winW > 0 && winH > 0) ? winW * winH : 0;

    // ---- phase 1: geometry over window, compact candidates to shared ----
    for (int j0 = 0; j0 < winN; j0 += LBLOCK){
        int j = j0 + tid;
        unsigned int dv = 0; unsigned int iv = 0; bool cand = false;
        if (j < winN){
            int r = j / winW;
            int c = j - r*winW;
            int hh = h0 + r, ww = w0 + c;
            float px = (ww+0.5f)*stride;
            float py = (hh+0.5f)*stride;
            float d1 = (px-Bx)*(Ay-By) - (Ax-Bx)*(py-By);
            float d2 = (px-Cx)*(By-Cy) - (Bx-Cx)*(py-Cy);
            float d3 = (px-Ax)*(Cy-Ay) - (Cx-Ax)*(py-Ay);
            bool hneg = (d1<0.f)||(d2<0.f)||(d3<0.f);
            bool hpos = (d1>0.f)||(d2>0.f)||(d3>0.f);
            bool inside = !(hneg&&hpos);
            float dist = fminf(segd(px,py,Ax,Ay,Bx,By),
                         fminf(segd(px,py,Bx,By,Cx,Cy),
                               segd(px,py,Cx,Cy,Ax,Ay)));
            if (inside || dist<=3.0f){
                cand = true;
                dv = __float_as_uint(dist);
                iv = (unsigned)((hh<<logW)|ww);
            }
        }
        unsigned bal = __ballot_sync(FULLMASK, cand);
        int wc = __popc(bal);
        if (wc){
            unsigned base = 0;
            if (lane==0) base = atomicAdd(&sh_n,(unsigned)wc);
            base = __shfl_sync(FULLMASK, base, 0);
            if (cand){
                unsigned pos = base + __popc(bal & ((1u<<lane)-1));
                if (pos < CAP){ sdist[pos]=dv; sidx[pos]=(unsigned short)iv; }
            }
        }
    }
    __syncthreads();
    const int n = min((int)sh_n, CAP);
    const bool accept_all = (n <= 96);

    // warp-0 scan+pick over 256 bins; writes sh_sel/sh_newk/sh_selcnt
    auto scanpick = [&](int k){
        if (tid < 32){
            unsigned v[8]; unsigned run=0;
            #pragma unroll
            for (int u=0;u<8;u++){ run += sh_hist[lane*8+u]; v[u]=run; }
            unsigned p = run;
            #pragma unroll
            for (int off=1;off<32;off<<=1){
                unsigned nn = __shfl_up_sync(FULLMASK,p,off);
                if (lane>=off) p += nn;
            }
            unsigned excl = p - run;
            #pragma unroll
            for (int u=0;u<8;u++){
                unsigned cum  = excl + v[u];
                unsigned prev = excl + (u? v[u-1] : 0u);
                if (cum >= (unsigned)k && prev < (unsigned)k){
                    sh_sel = lane*8+u; sh_newk = k - prev; sh_selcnt = cum - prev;
                }
            }
        }
    };

    // ---- phase 2: radix select of 96th smallest (dist, then idx tiebreak) ----
    unsigned int D  = 0xFFFFFFFFu;   // pivot dist bits
    unsigned int Ti = 0xFFFFu;       // idx threshold among dist==D
    if (!accept_all){
        unsigned pref = 0;
        int k = 96;
        bool done = false;
        for (int shift=24; shift>=0 && !done; shift-=8){
            if (tid < 256) sh_hist[tid] = 0;
            __syncthreads();
            for (int j0=0; j0<n; j0+=LBLOCK){
                int j = j0 + tid;
                unsigned bin = 0xFFFFFFFFu;
                if (j < n){
                    unsigned dv = sdist[j];
                    if (shift==24 || (dv>>(shift+8)) == pref)
                        bin = (dv>>shift)&0xFF;
                }
                unsigned mm = __match_any_sync(FULLMASK, bin);
                if (bin != 0xFFFFFFFFu && lane == (__ffs(mm)-1))
                    atomicAdd(&sh_hist[bin], (unsigned)__popc(mm));
            }
            __syncthreads();
            scanpick(k);
            __syncthreads();
            unsigned sel = sh_sel; k = (int)sh_newk; unsigned ceq = sh_selcnt;
            pref = (pref<<8) | sel;
            if (ceq == 1u){
                // unique element owns this prefix -> it IS the k-th; no dist ties
                for (int j=tid; j<n; j+=LBLOCK)
                    if ((sdist[j]>>shift) == pref) sh_kd = sdist[j];
                __syncthreads();
                D = sh_kd;          // Ti stays max
                done = true;
            } else if (shift==0){
                D = pref;           // exact pivot dist; ceq elements share it
                if ((unsigned)k != ceq){
                    // idx tie-break: select k-th smallest idx among dist==D
                    unsigned ipref = 0;
                    for (int s2=8; s2>=0; s2-=8){
                        if (tid < 256) sh_hist[tid] = 0;
                        __syncthreads();
                        for (int j0=0; j0<n; j0+=LBLOCK){
                            int j = j0 + tid;
                            unsigned bin = 0xFFFFFFFFu;
                            if (j < n && sdist[j] == D){
                                unsigned ivv = sidx[j];
                                if (s2==8 || (ivv>>8) == ipref)
                                    bin = (ivv>>s2)&0xFF;
                            }
                            unsigned mm = __match_any_sync(FULLMASK, bin);
                            if (bin != 0xFFFFFFFFu && lane == (__ffs(mm)-1))
                                atomicAdd(&sh_hist[bin], (unsigned)__popc(mm));
                        }
                        __syncthreads();
                        scanpick(k);
                        __syncthreads();
                        ipref = (ipref<<8) | sh_sel; k = (int)sh_newk;
                    }
                    Ti = ipref;
                } // else: accept all dist==D (Ti stays max)
                done = true;
            }
        }
    }

    // ---- phase 3: accumulate over accepted candidates ----
    float regsum=0.f, clssum=0.f; int cnt=0;
    const float* rbase = preg + (size_t)b*6*HW;
    const float* cbase = pcls + (size_t)b*HW;
    unsigned int* mbase = g_mask + moff + b*(HW>>5);
    for (int j=tid; j<n; j+=LBLOCK){
        unsigned dv = sdist[j];
        unsigned ivv = sidx[j];
        if (!accept_all){
            if (dv > D) continue;
            if (dv == D && ivv > Ti) continue;
        }
        int idx = (int)ivv;
        int hh = idx >> logW, ww = idx & (W-1);
        float px=(ww+0.5f)*stride, py=(hh+0.5f)*stride;
        float g0x=(Ax-px)*inv, g0y=(Ay-py)*inv;
        float g1x=(Bx-px)*inv, g1y=(By-py)*inv;
        float g2x=(Cx-px)*inv, g2y=(Cy-py)*inv;
        float p0x = rbase[idx],        p0y = rbase[HW+idx];
        float p1x = rbase[2*HW+idx],   p1y = rbase[3*HW+idx];
        float p2x = rbase[4*HW+idx],   p2y = rbase[5*HW+idx];
        float p0 = (p0x-g0x)*(p0x-g0x) + (p0y-g0y)*(p0y-g0y);
        float d00 = sqrtf((p1x-g1x)*(p1x-g1x)+(p1y-g1y)*(p1y-g1y));
        float d01 = sqrtf((p1x-g2x)*(p1x-g2x)+(p1y-g2y)*(p1y-g2y));
        float d10 = sqrtf((p2x-g1x)*(p2x-g1x)+(p2y-g1y)*(p2y-g1y));
        float d11 = sqrtf((p2x-g2x)*(p2x-g2x)+(p2y-g2y)*(p2y-g2y));
        float cd = fminf(d00,d01)+fminf(d10,d11)+fminf(d00,d10)+fminf(d01,d11);
        regsum += p0 + cd;            // LAMBDA_P0 = LAMBDA_CD = 1
        clssum += sp(-cbase[idx]);
        cnt++;
        atomicOr(&mbase[idx>>5], 1u<<(idx&31));
    }
    for (int off=16;off;off>>=1){
        regsum += __shfl_xor_sync(FULLMASK,regsum,off);
        clssum += __shfl_xor_sync(FULLMASK,clssum,off);
        cnt    += __shfl_xor_sync(FULLMASK,cnt,off);
    }
    if (lane==0 && cnt){
        atomicAdd(&s_reg,regsum); atomicAdd(&s_cls,clssum); atomicAdd(&s_cnt,cnt);
    }
    __syncthreads();
    if (tid==0 && s_cnt){
        atomicAdd(&g_reg,(double)s_reg);
        atomicAdd(&g_cls,(double)s_cls);
        atomicAdd(&g_pc,(unsigned long long)s_cnt);
    }
}

// single fused obj pass (float4) over all three levels + folded finalize
__global__ __launch_bounds__(256) void obj_all(
    const float* __restrict__ o0,
    const float* __restrict__ o1,
    const float* __restrict__ o2,
    float* __restrict__ out)
{
    const int tid = threadIdx.x;
    const int lane = tid & 31;
    float sum = 0.f; int ot = 0;
    // 344064 floats = 86016 float4; level boundaries (262144, 327680) are /4
    for (int v = blockIdx.x*256 + tid; v < 86016; v += OBJ_BLOCKS*256){
        int i = v*4;
        const float* p; int local, logHW, moff;
        if (i < 262144){ p=o0; local=i;        logHW=14; moff=0;     }
        else if (i < 327680){ p=o1; local=i-262144; logHW=12; moff=8192; }
        else { p=o2; local=i-327680; logHW=10; moff=10240; }
        int b  = local >> logHW;
        int hw = local & ((1<<logHW)-1);
        float4 x = *(const float4*)(p + local);
        unsigned wrd = g_mask[moff + b*(1<<(logHW-5)) + (hw>>5)];
        unsigned sh = (unsigned)(hw & 31);
        unsigned b0 = (wrd >> sh) & 1u;
        unsigned b1 = (wrd >> (sh+1)) & 1u;
        unsigned b2 = (wrd >> (sh+2)) & 1u;
        unsigned b3 = (wrd >> (sh+3)) & 1u;
        sum += b0 ? 1.2f*sp(-x.x) : sp(x.x);
        sum += b1 ? 1.2f*sp(-x.y) : sp(x.y);
        sum += b2 ? 1.2f*sp(-x.z) : sp(x.z);
        sum += b3 ? 1.2f*sp(-x.w) : sp(x.w);
        ot  += (int)(b0+b1+b2+b3);
    }
    for (int off=16;off;off>>=1){
        sum += __shfl_xor_sync(FULLMASK,sum,off);
        ot  += __shfl_xor_sync(FULLMASK,ot,off);
    }
    __shared__ float s_sum; __shared__ int s_ot;
    if (tid==0){ s_sum=0.f; s_ot=0; }
    __syncthreads();
    if (lane==0){ atomicAdd(&s_sum,sum); atomicAdd(&s_ot,ot); }
    __syncthreads();
    if (tid==0){
        atomicAdd(&g_obj,(double)s_sum);
        atomicAdd(&g_objt,(unsigned long long)s_ot);
        __threadfence();
        unsigned ticket = atomicAdd(&g_done, 1u);
        if (ticket == OBJ_BLOCKS-1){
            double pc = (double)g_pc; if (pc < 1.0) pc = 1.0;
            double nc = 344064.0 - (double)g_objt; if (nc < 1.0) nc = 1.0;
            out[0] = (float)(g_reg/pc + g_obj/(pc+nc) + g_cls/pc);
        }
    }
}

__global__ void zero_kernel(){
    int i = blockIdx.x*blockDim.x+threadIdx.x;
    if (i==0){ g_reg=0.0; g_cls=0.0; g_obj=0.0; g_pc=0ull; g_objt=0ull; g_done=0u; }
    for (int j=i; j<MASK_WORDS; j+=blockDim.x*gridDim.x) g_mask[j]=0u;
}

extern "C" void kernel_launch(void* const* d_in, const int* in_sizes, int n_in,
                              void* d_out, int out_size)
{
    const float* reg0 = (const float*)d_in[0];
    const float* obj0 = (const float*)d_in[1];
    const float* cls0 = (const float*)d_in[2];
    const float* reg1 = (const float*)d_in[3];
    const float* obj1 = (const float*)d_in[4];
    const float* cls1 = (const float*)d_in[5];
    const float* reg2 = (const float*)d_in[6];
    const float* obj2 = (const float*)d_in[7];
    const float* cls2 = (const float*)d_in[8];
    const float* gt   = (const float*)d_in[9];
    float* out = (float*)d_out;

    const int smem = CAP*4 + 256*4 + CAP*2;   // 56320 bytes
    static int attr_set = 0;
    if (!attr_set){
        cudaFuncSetAttribute(level_all,
            cudaFuncAttributeMaxDynamicSharedMemorySize, smem);
        attr_set = 1;
    }

    zero_kernel<<<42,256>>>();
    level_all<<<1536,LBLOCK,smem>>>(reg0, cls0, reg1, cls1, reg2, cls2, gt);
    obj_all<<<OBJ_BLOCKS,256>>>(obj0, obj1, obj2, out);
}

// round 4
// speedup vs baseline: 3.7424x; 1.2111x over previous
#include <cuda_runtime.h>
#include <cstdint>

#define FULLMASK 0xffffffffu
#define CAP 9216          // hard upper bound on candidates per (b,g) at L0
#define LBLOCK 512
#define OBJ_BLOCKS 336

// ---------------- global scratch (no allocs allowed) ----------------
// All state is self-cleaning: starts zeroed (static init), and every
// invocation resets what it used, so graph replays stay deterministic.
__device__ double g_reg, g_cls, g_obj;
__device__ unsigned long long g_pc, g_objt;
__device__ unsigned int g_done;
#define MASK_WORDS 10752   // 8192 (L0) + 2048 (L1) + 512 (L2)
__device__ unsigned int g_mask[MASK_WORDS];

// stable softplus, matches jax.nn.softplus
__device__ __forceinline__ float sp(float x){
    return fmaxf(x, 0.0f) + log1pf(expf(-fabsf(x)));
}

// One block per (level, b, g). 1536 blocks; L0 first (largest work).
__global__ __launch_bounds__(LBLOCK) void level_all(
    const float* __restrict__ reg0, const float* __restrict__ cls0,
    const float* __restrict__ reg1, const float* __restrict__ cls1,
    const float* __restrict__ reg2, const float* __restrict__ cls2,
    const float* __restrict__ gt)
{
    extern __shared__ unsigned int smem_raw[];
    unsigned int*      sdist  = smem_raw;                    // CAP u32
    unsigned int*      sh_hist= smem_raw + CAP;              // 256 u32
    unsigned short*    sidx   = (unsigned short*)(smem_raw + CAP + 256); // CAP u16
    __shared__ unsigned int sh_n, sh_sel, sh_newk, sh_selcnt, sh_kd;
    __shared__ float s_reg, s_cls; __shared__ int s_cnt;

    const int lv   = blockIdx.x >> 9;
    const int pair = blockIdx.x & 511;
    const int b    = pair >> 5;            // Ng = 32
    const int tid  = threadIdx.x;
    const int lane = tid & 31;

    int W, logW, moff; float stride;
    const float *preg, *pcls;
    if (lv==0){ W=128; logW=7; moff=0;     stride= 8.f; preg=reg0; pcls=cls0; }
    else if (lv==1){ W=64; logW=6; moff=8192;  stride=16.f; preg=reg1; pcls=cls1; }
    else       { W=32; logW=5; moff=10240; stride=32.f; preg=reg2; pcls=cls2; }
    const int H  = W;
    const int HW = 1 << (2*logW);

    if (tid==0){ sh_n=0; s_reg=0.f; s_cls=0.f; s_cnt=0; }
    __syncthreads();

    const float* t = gt + (size_t)pair * 6;
    const float Ax=t[0],Ay=t[1],Bx=t[2],By=t[3],Cx=t[4],Cy=t[5];

    // ---- per-triangle constants (hoisted out of the cell loop) ----
    // sign tests: d = px*ca + py*cb + cc
    const float c1a = Ay-By, c1b = -(Ax-Bx), c1c = -Bx*(Ay-By) + By*(Ax-Bx);
    const float c2a = By-Cy, c2b = -(Bx-Cx), c2c = -Cx*(By-Cy) + Cy*(Bx-Cx);
    const float c3a = Cy-Ay, c3b = -(Cx-Ax), c3c = -Ax*(Cy-Ay) + Ay*(Cx-Ax);
    // segment vectors + reciprocal squared lengths (replaces per-cell divides)
    const float v0x=Bx-Ax, v0y=By-Ay, r0 = 1.0f/(v0x*v0x+v0y*v0y+1e-9f);
    const float v1x=Cx-Bx, v1y=Cy-By, r1 = 1.0f/(v1x*v1x+v1y*v1y+1e-9f);
    const float v2x=Ax-Cx, v2y=Ay-Cy, r2 = 1.0f/(v2x*v2x+v2y*v2y+1e-9f);

    // bbox expanded by ETA(=3) -> cell window (conservative +/-1 cell)
    float xmn = fminf(Ax,fminf(Bx,Cx)) - 3.0f;
    float xmx = fmaxf(Ax,fmaxf(Bx,Cx)) + 3.0f;
    float ymn = fminf(Ay,fminf(By,Cy)) - 3.0f;
    float ymx = fmaxf(Ay,fmaxf(By,Cy)) + 3.0f;
    float inv = 1.0f/stride;
    int w0 = max(0,   (int)floorf(xmn*inv - 0.5f) - 1);
    int w1 = min(W-1, (int)ceilf (xmx*inv - 0.5f) + 1);
    int h0 = max(0,   (int)floorf(ymn*inv - 0.5f) - 1);
    int h1 = min(H-1, (int)ceilf (ymx*inv - 0.5f) + 1);
    int winW = w1 - w0 + 1;
    int winH = h1 - h0 + 1;
    int winN = (winW > 0 && winH > 0) ? winW * winH : 0;
    float winWr = 1.0f / (float)winW;

    // ---- phase 1: geometry over window, compact candidates to shared ----
    for (int j0 = 0; j0 < winN; j0 += LBLOCK){
        int j = j0 + tid;
        unsigned int dv = 0; unsigned int iv = 0; bool cand = false;
        if (j < winN){
            // j / winW via float reciprocal + exact fixup
            int r = (int)((float)j * winWr);
            int c = j - r*winW;
            if (c < 0)          { r--; c += winW; }
            else if (c >= winW) { r++; c -= winW; }
            int hh = h0 + r, ww = w0 + c;
            float px = (ww+0.5f)*stride;
            float py = (hh+0.5f)*stride;
            float d1 = px*c1a + py*c1b + c1c;
            float d2 = px*c2a + py*c2b + c2c;
            float d3 = px*c3a + py*c3b + c3c;
            bool hneg = (d1<0.f)||(d2<0.f)||(d3<0.f);
            bool hpos = (d1>0.f)||(d2>0.f)||(d3>0.f);
            bool inside = !(hneg&&hpos);
            // squared point-segment distances (min commutes with +eps,sqrt)
            float wx, wy, tt, dx, dy;
            wx=px-Ax; wy=py-Ay; tt=fminf(fmaxf((wx*v0x+wy*v0y)*r0,0.f),1.f);
            dx=wx-tt*v0x; dy=wy-tt*v0y; float s0=dx*dx+dy*dy;
            wx=px-Bx; wy=py-By; tt=fminf(fmaxf((wx*v1x+wy*v1y)*r1,0.f),1.f);
            dx=wx-tt*v1x; dy=wy-tt*v1y; float s1=dx*dx+dy*dy;
            wx=px-Cx; wy=py-Cy; tt=fminf(fmaxf((wx*v2x+wy*v2y)*r2,0.f),1.f);
            dx=wx-tt*v2x; dy=wy-tt*v2y; float s2=dx*dx+dy*dy;
            float dist = sqrtf(fminf(s0,fminf(s1,s2)) + 1e-12f);
            if (inside || dist<=3.0f){
                cand = true;
                dv = __float_as_uint(dist);
                iv = (unsigned)((hh<<logW)|ww);
            }
        }
        unsigned bal = __ballot_sync(FULLMASK, cand);
        int wc = __popc(bal);
        if (wc){
            unsigned base = 0;
            if (lane==0) base = atomicAdd(&sh_n,(unsigned)wc);
            base = __shfl_sync(FULLMASK, base, 0);
            if (cand){
                unsigned pos = base + __popc(bal & ((1u<<lane)-1));
                if (pos < CAP){ sdist[pos]=dv; sidx[pos]=(unsigned short)iv; }
            }
        }
    }
    __syncthreads();
    const int n = min((int)sh_n, CAP);
    const bool accept_all = (n <= 96);

    // warp-0 scan+pick over 256 bins; writes sh_sel/sh_newk/sh_selcnt
    auto scanpick = [&](int k){
        if (tid < 32){
            unsigned v[8]; unsigned run=0;
            #pragma unroll
            for (int u=0;u<8;u++){ run += sh_hist[lane*8+u]; v[u]=run; }
            unsigned p = run;
            #pragma unroll
            for (int off=1;off<32;off<<=1){
                unsigned nn = __shfl_up_sync(FULLMASK,p,off);
                if (lane>=off) p += nn;
            }
            unsigned excl = p - run;
            #pragma unroll
            for (int u=0;u<8;u++){
                unsigned cum  = excl + v[u];
                unsigned prev = excl + (u? v[u-1] : 0u);
                if (cum >= (unsigned)k && prev < (unsigned)k){
                    sh_sel = lane*8+u; sh_newk = k - prev; sh_selcnt = cum - prev;
                }
            }
        }
    };

    // ---- phase 2: radix select of 96th smallest (dist, then idx tiebreak) ----
    unsigned int D  = 0xFFFFFFFFu;   // pivot dist bits
    unsigned int Ti = 0xFFFFu;       // idx threshold among dist==D
    if (!accept_all){
        unsigned pref = 0;
        int k = 96;
        bool done = false;
        for (int shift=24; shift>=0 && !done; shift-=8){
            if (tid < 256) sh_hist[tid] = 0;
            __syncthreads();
            for (int j0=0; j0<n; j0+=LBLOCK){
                int j = j0 + tid;
                unsigned bin = 0xFFFFFFFFu;
                if (j < n){
                    unsigned dv = sdist[j];
                    if (shift==24 || (dv>>(shift+8)) == pref)
                        bin = (dv>>shift)&0xFF;
                }
                unsigned mm = __match_any_sync(FULLMASK, bin);
                if (bin != 0xFFFFFFFFu && lane == (__ffs(mm)-1))
                    atomicAdd(&sh_hist[bin], (unsigned)__popc(mm));
            }
            __syncthreads();
            scanpick(k);
            __syncthreads();
            unsigned sel = sh_sel; k = (int)sh_newk; unsigned ceq = sh_selcnt;
            pref = (pref<<8) | sel;
            if (ceq == 1u){
                // unique element owns this prefix -> it IS the k-th; no dist ties
                for (int j=tid; j<n; j+=LBLOCK)
                    if ((sdist[j]>>shift) == pref) sh_kd = sdist[j];
                __syncthreads();
                D = sh_kd;          // Ti stays max
                done = true;
            } else if (shift==0){
                D = pref;           // exact pivot dist; ceq elements share it
                if ((unsigned)k != ceq){
                    // idx tie-break: select k-th smallest idx among dist==D
                    unsigned ipref = 0;
                    for (int s2=8; s2>=0; s2-=8){
                        if (tid < 256) sh_hist[tid] = 0;
                        __syncthreads();
                        for (int j0=0; j0<n; j0+=LBLOCK){
                            int j = j0 + tid;
                            unsigned bin = 0xFFFFFFFFu;
                            if (j < n && sdist[j] == D){
                                unsigned ivv = sidx[j];
                                if (s2==8 || (ivv>>8) == ipref)
                                    bin = (ivv>>s2)&0xFF;
                            }
                            unsigned mm = __match_any_sync(FULLMASK, bin);
                            if (bin != 0xFFFFFFFFu && lane == (__ffs(mm)-1))
                                atomicAdd(&sh_hist[bin], (unsigned)__popc(mm));
                        }
                        __syncthreads();
                        scanpick(k);
                        __syncthreads();
                        ipref = (ipref<<8) | sh_sel; k = (int)sh_newk;
                    }
                    Ti = ipref;
                } // else: accept all dist==D (Ti stays max)
                done = true;
            }
        }
    }

    // ---- phase 3: accumulate over accepted candidates ----
    float regsum=0.f, clssum=0.f; int cnt=0;
    const float* rbase = preg + (size_t)b*6*HW;
    const float* cbase = pcls + (size_t)b*HW;
    unsigned int* mbase = g_mask + moff + b*(HW>>5);
    for (int j=tid; j<n; j+=LBLOCK){
        unsigned dv = sdist[j];
        unsigned ivv = sidx[j];
        if (!accept_all){
            if (dv > D) continue;
            if (dv == D && ivv > Ti) continue;
        }
        int idx = (int)ivv;
        int hh = idx >> logW, ww = idx & (W-1);
        float px=(ww+0.5f)*stride, py=(hh+0.5f)*stride;
        float g0x=(Ax-px)*inv, g0y=(Ay-py)*inv;
        float g1x=(Bx-px)*inv, g1y=(By-py)*inv;
        float g2x=(Cx-px)*inv, g2y=(Cy-py)*inv;
        float p0x = rbase[idx],        p0y = rbase[HW+idx];
        float p1x = rbase[2*HW+idx],   p1y = rbase[3*HW+idx];
        float p2x = rbase[4*HW+idx],   p2y = rbase[5*HW+idx];
        float p0 = (p0x-g0x)*(p0x-g0x) + (p0y-g0y)*(p0y-g0y);
        float d00 = sqrtf((p1x-g1x)*(p1x-g1x)+(p1y-g1y)*(p1y-g1y));
        float d01 = sqrtf((p1x-g2x)*(p1x-g2x)+(p1y-g2y)*(p1y-g2y));
        float d10 = sqrtf((p2x-g1x)*(p2x-g1x)+(p2y-g1y)*(p2y-g1y));
        float d11 = sqrtf((p2x-g2x)*(p2x-g2x)+(p2y-g2y)*(p2y-g2y));
        float cd = fminf(d00,d01)+fminf(d10,d11)+fminf(d00,d10)+fminf(d01,d11);
        regsum += p0 + cd;            // LAMBDA_P0 = LAMBDA_CD = 1
        clssum += sp(-cbase[idx]);
        cnt++;
        atomicOr(&mbase[idx>>5], 1u<<(idx&31));
    }
    for (int off=16;off;off>>=1){
        regsum += __shfl_xor_sync(FULLMASK,regsum,off);
        clssum += __shfl_xor_sync(FULLMASK,clssum,off);
        cnt    += __shfl_xor_sync(FULLMASK,cnt,off);
    }
    if (lane==0 && cnt){
        atomicAdd(&s_reg,regsum); atomicAdd(&s_cls,clssum); atomicAdd(&s_cnt,cnt);
    }
    __syncthreads();
    if (tid==0 && s_cnt){
        atomicAdd(&g_reg,(double)s_reg);
        atomicAdd(&g_cls,(double)s_cls);
        atomicAdd(&g_pc,(unsigned long long)s_cnt);
    }
}

// single fused obj pass (float4) over all three levels + folded finalize.
// Self-cleaning: zeroes each mask word after reading it; last block resets
// all scalar accumulators after computing the output.
__global__ __launch_bounds__(256) void obj_all(
    const float* __restrict__ o0,
    const float* __restrict__ o1,
    const float* __restrict__ o2,
    float* __restrict__ out)
{
    const int tid = threadIdx.x;
    const int lane = tid & 31;
    float sum = 0.f; int ot = 0;
    // 344064 floats = 86016 float4; level boundaries (262144, 327680) are /1024
    for (int v = blockIdx.x*256 + tid; v < 86016; v += OBJ_BLOCKS*256){
        int i = v*4;
        const float* p; int local, logHW, moff;
        if (i < 262144){ p=o0; local=i;        logHW=14; moff=0;     }
        else if (i < 327680){ p=o1; local=i-262144; logHW=12; moff=8192; }
        else { p=o2; local=i-327680; logHW=10; moff=10240; }
        int b  = local >> logHW;
        int hw = local & ((1<<logHW)-1);
        float4 x = *(const float4*)(p + local);
        unsigned int* wp = &g_mask[moff + b*(1<<(logHW-5)) + (hw>>5)];
        unsigned wrd = *wp;
        // zero after read: the 8 reader threads of this word are in the same
        // warp (consecutive v), so their loads issue before this store.
        if ((v & 7) == 0) *wp = 0u;
        unsigned sh = (unsigned)(hw & 31);
        unsigned b0 = (wrd >> sh) & 1u;
        unsigned b1 = (wrd >> (sh+1)) & 1u;
        unsigned b2 = (wrd >> (sh+2)) & 1u;
        unsigned b3 = (wrd >> (sh+3)) & 1u;
        sum += b0 ? 1.2f*sp(-x.x) : sp(x.x);
        sum += b1 ? 1.2f*sp(-x.y) : sp(x.y);
        sum += b2 ? 1.2f*sp(-x.z) : sp(x.z);
        sum += b3 ? 1.2f*sp(-x.w) : sp(x.w);
        ot  += (int)(b0+b1+b2+b3);
    }
    for (int off=16;off;off>>=1){
        sum += __shfl_xor_sync(FULLMASK,sum,off);
        ot  += __shfl_xor_sync(FULLMASK,ot,off);
    }
    __shared__ float s_sum; __shared__ int s_ot;
    if (tid==0){ s_sum=0.f; s_ot=0; }
    __syncthreads();
    if (lane==0){ atomicAdd(&s_sum,sum); atomicAdd(&s_ot,ot); }
    __syncthreads();
    if (tid==0){
        atomicAdd(&g_obj,(double)s_sum);
        atomicAdd(&g_objt,(unsigned long long)s_ot);
        __threadfence();
        unsigned ticket = atomicAdd(&g_done, 1u);
        if (ticket == OBJ_BLOCKS-1){
            double pc = (double)g_pc; if (pc < 1.0) pc = 1.0;
            double nc = 344064.0 - (double)g_objt; if (nc < 1.0) nc = 1.0;
            out[0] = (float)(g_reg/pc + g_obj/(pc+nc) + g_cls/pc);
            // reset all scalar state for the next (deterministic) replay
            g_reg = 0.0; g_cls = 0.0; g_obj = 0.0;
            g_pc = 0ull; g_objt = 0ull;
            __threadfence();
            g_done = 0u;
        }
    }
}

extern "C" void kernel_launch(void* const* d_in, const int* in_sizes, int n_in,
                              void* d_out, int out_size)
{
    const float* reg0 = (const float*)d_in[0];
    const float* obj0 = (const float*)d_in[1];
    const float* cls0 = (const float*)d_in[2];
    const float* reg1 = (const float*)d_in[3];
    const float* obj1 = (const float*)d_in[4];
    const float* cls1 = (const float*)d_in[5];
    const float* reg2 = (const float*)d_in[6];
    const float* obj2 = (const float*)d_in[7];
    const float* cls2 = (const float*)d_in[8];
    const float* gt   = (const float*)d_in[9];
    float* out = (float*)d_out;

    const int smem = CAP*4 + 256*4 + CAP*2;   // 56320 bytes
    static int attr_set = 0;
    if (!attr_set){
        cudaFuncSetAttribute(level_all,
            cudaFuncAttributeMaxDynamicSharedMemorySize, smem);
        attr_set = 1;
    }

    level_all<<<1536,LBLOCK,smem>>>(reg0, cls0, reg1, cls1, reg2, cls2, gt);
    obj_all<<<OBJ_BLOCKS,256>>>(obj0, obj1, obj2, out);
}